// round 14
// baseline (speedup 1.0000x reference)
#include <cuda_runtime.h>
#include <cuda_fp16.h>
#include <cstdint>

// ---------------------------------------------------------------------------
// Problem constants
// ---------------------------------------------------------------------------
static constexpr int B_  = 4;
static constexpr int C_  = 64;
static constexpr int H_  = 256;
static constexpr int W_  = 512;
static constexpr int HW  = H_ * W_;               // 131072 = 2^17
static constexpr int SW_ = 3 * W_;                // 1536
static constexpr int TILE_P = 512;                // one full image row
static constexpr int TILES_PER_B = HW / TILE_P;   // 256
static constexpr int N_TILES = B_ * TILES_PER_B;  // 1024
static constexpr int THREADS = 576;               // 2 producer + 16 consumer warps

// A stages: 512 px rows x 144B pitch (128B data + 16B pad, ldmatrix-friendly)
static constexpr int A_PITCH_B = 144;
static constexpr int A_BYTES   = TILE_P * A_PITCH_B;        // 73728
// W: per-thread B-fragment records: [tap][ks][lane] 64B, chunk-XOR swizzled
static constexpr int W_TAP_B   = 4 * 2048;                  // 8192
static constexpr int W_BYTES   = 9 * W_TAP_B;               // 73728

static constexpr int SMEM_W    = 0;
static constexpr int SMEM_BIAS = W_BYTES;                   // 256 B
static constexpr int SMEM_BAR  = W_BYTES + 256;             // 4 x 8B mbarriers
static constexpr int SMEM_A    = W_BYTES + 512;             // 74240 (128-aligned)
static constexpr int SMEM_TOTAL = SMEM_A + 2 * A_BYTES;     // 221696

__device__ int    g_idx_is64;
__device__ __align__(128) __half g_xt[(size_t)B_ * HW * C_];  // [B][HW][C] fp16

// ---------------------------------------------------------------------------
// PTX helpers
// ---------------------------------------------------------------------------
__device__ __forceinline__ uint32_t smem_u32(const void* p) {
    uint32_t a;
    asm("{ .reg .u64 t; cvta.to.shared.u64 t, %1; cvt.u32.u64 %0, t; }" : "=r"(a) : "l"(p));
    return a;
}

__device__ __forceinline__ void ldmatrix_x4(uint32_t* r, uint32_t addr) {
    asm volatile("ldmatrix.sync.aligned.m8n8.x4.shared.b16 {%0,%1,%2,%3}, [%4];"
                 : "=r"(r[0]), "=r"(r[1]), "=r"(r[2]), "=r"(r[3]) : "r"(addr));
}

__device__ __forceinline__ void lds128(uint32_t* q, uint32_t addr) {
    asm volatile("ld.shared.v4.b32 {%0,%1,%2,%3}, [%4];"
                 : "=r"(q[0]), "=r"(q[1]), "=r"(q[2]), "=r"(q[3]) : "r"(addr));
}

__device__ __forceinline__ void mma_f16(float* c, const uint32_t* a, uint32_t b0, uint32_t b1) {
    asm volatile(
        "mma.sync.aligned.m16n8k16.row.col.f32.f16.f16.f32 "
        "{%0,%1,%2,%3}, {%4,%5,%6,%7}, {%8,%9}, {%0,%1,%2,%3};"
        : "+f"(c[0]), "+f"(c[1]), "+f"(c[2]), "+f"(c[3])
        : "r"(a[0]), "r"(a[1]), "r"(a[2]), "r"(a[3]), "r"(b0), "r"(b1));
}

__device__ __forceinline__ void sts128(uint32_t addr, float4 v) {
    asm volatile("st.shared.v4.b32 [%0], {%1,%2,%3,%4};"
                 :: "r"(addr), "f"(v.x), "f"(v.y), "f"(v.z), "f"(v.w) : "memory");
}

#define MBARRIER_INIT(bar, cnt) \
    asm volatile("mbarrier.init.shared.b64 [%0], %1;" :: "r"(bar), "r"((uint32_t)(cnt)) : "memory")

#define MBARRIER_ARRIVE(bar) \
    asm volatile("mbarrier.arrive.shared.b64 _, [%0];" :: "r"(bar) : "memory")

#define MBARRIER_WAIT_PARITY(bar, ph) do {                                              \
    uint32_t _m = (bar); uint32_t _p = (ph); uint32_t _d;                               \
    asm volatile("{\n\t.reg .pred p;\n\t"                                               \
        "mbarrier.try_wait.parity.acquire.cta.shared::cta.b64 p, [%1], %2;\n\t"         \
        "selp.b32 %0, 1, 0, p;\n\t}" : "=r"(_d) : "r"(_m), "r"(_p) : "memory");         \
    if (!_d) {                                                                          \
        asm volatile("{\n\t.reg .pred P1;\n\t"                                          \
            "WL_%=:\n\t"                                                                \
            "mbarrier.try_wait.parity.acquire.cta.shared::cta.b64 P1, [%0], %1, 0x989680;\n\t" \
            "@P1 bra.uni WD_%=;\n\t"                                                    \
            "bra.uni WL_%=;\n\t"                                                        \
            "WD_%=:\n\t}" :: "r"(_m), "r"(_p) : "memory");                              \
    }                                                                                   \
} while (0)

// ---------------------------------------------------------------------------
// Kernel 1: transpose x [B][C][HW] -> g_xt [B][HW][C] fp16; block (0,0,0)
//           also detects idx dtype (int64 vs int32).
// ---------------------------------------------------------------------------
__global__ void transpose_kernel(const float* __restrict__ x,
                                 const unsigned int* __restrict__ idxw) {
    if (blockIdx.x == 0 && blockIdx.y == 0 && blockIdx.z == 0 &&
        threadIdx.x == 0 && threadIdx.y == 0) {
        int is64 = 1;
        for (int i = 0; i < 64; ++i)
            if (idxw[2 * i + 1] != 0u) { is64 = 0; break; }
        g_idx_is64 = is64;
    }
    __shared__ float t[32][33];
    const int b  = blockIdx.z;
    const int cb = blockIdx.y * 32;
    const int gb = blockIdx.x * 32;
    const int tx = threadIdx.x, ty = threadIdx.y;
    const float* xb = x + (size_t)b * C_ * HW;
#pragma unroll
    for (int i = 0; i < 32; i += 8)
        t[ty + i][tx] = xb[(size_t)(cb + ty + i) * HW + gb + tx];
    __syncthreads();
    __half* xtb = g_xt + ((size_t)b * HW) * C_;
    const int c2  = tx & 15;
    const int sel = tx >> 4;
#pragma unroll
    for (int i = 0; i < 2; ++i) {
        int hwl = ty * 4 + sel * 2 + i;
        __half2 v = __floats2half2_rn(t[2 * c2][hwl], t[2 * c2 + 1][hwl]);
        *(__half2*)(xtb + (size_t)(gb + hwl) * C_ + cb + 2 * c2) = v;
    }
}

// ---------------------------------------------------------------------------
// Kernel 2: warp-specialized persistent kernel.
//   Producers (warps 0-1): gather LDG.128 -> STS.128 into 2-stage ring.
//   Consumers (warps 2-17): ldmatrix + vectorized B LDS + fp16 mma.sync.
//   mbarrier full/empty ring; no __syncthreads in the loop.
// ---------------------------------------------------------------------------
struct Cur { int tile; int tap; };
__device__ __forceinline__ void adv(Cur& c, int stride) {
    if (++c.tap == 9) { c.tap = 0; c.tile += stride; }
}

__device__ __forceinline__ float4 gather16(const void* idx, int is64,
                                           const Cur& c, int row, int lane7) {
    int pt = c.tile & (TILES_PER_B - 1);       // image row
    int kh = c.tap / 3;
    int kw = c.tap - kh * 3;
    int o  = (3 * pt + kh) * SW_ + 3 * row + kw;
    int g  = is64 ? (int)__ldg((const long long*)idx + o)
                  : __ldg((const int*)idx + o);
    const char* src = (const char*)g_xt
                    + ((((size_t)(c.tile >> 8)) << 17) + (uint32_t)g) * (C_ * 2)
                    + lane7 * 16;
    return __ldg((const float4*)src);
}

__global__ void __launch_bounds__(THREADS, 1)
latconv_main(const void* __restrict__ idx_raw,
             const float* __restrict__ wgt,
             const float* __restrict__ bias,
             float* __restrict__ out) {
    extern __shared__ char smem[];
    const uint32_t wbase = smem_u32(smem + SMEM_W);
    float* bsm = (float*)(smem + SMEM_BIAS);

    const int tid = threadIdx.x;
    const int wid = tid >> 5;       // 0..17
    const int lid = tid & 31;
    const int is64 = g_idx_is64;

    // Stage weights fp16 as per-thread B-fragment records (r12 layout).
    for (int e = tid; e < C_ * C_ * 9; e += THREADS) {
        int ci = e & 63, co = (e >> 6) & 63, j = e >> 12;
        int nt = co >> 3, gw = co & 7;
        int ks = ci >> 4, r = ci & 15;
        int bsel = r >> 3, tw = (r & 7) >> 1, lo = r & 1;
        int lane = gw * 4 + tw;
        int c = nt >> 1, u = ((nt & 1) << 1) + bsel;
        uint32_t off = (uint32_t)(j * W_TAP_B + ks * 2048 + lane * 64
                     + ((c ^ ((lane >> 1) & 3)) << 4) + (u << 2) + (lo << 1));
        *(__half*)(smem + SMEM_W + off) = __float2half_rn(wgt[co * 576 + ci * 9 + j]);
    }
    if (tid < C_) bsm[tid] = bias[tid];

    const uint32_t barb   = smem_u32(smem + SMEM_BAR);
    const uint32_t abase0 = smem_u32(smem + SMEM_A);
    if (tid == 0) {
        MBARRIER_INIT(barb + 0,  64);    // full[0]  (producer threads arrive)
        MBARRIER_INIT(barb + 8,  64);    // full[1]
        MBARRIER_INIT(barb + 16, 512);   // empty[0] (consumer threads arrive)
        MBARRIER_INIT(barb + 24, 512);   // empty[1]
    }
    __syncthreads();

    const int nloc = (N_TILES - (int)blockIdx.x + (int)gridDim.x - 1) / (int)gridDim.x;
    const int S = nloc * 9;
    if (S == 0) return;

    if (wid < 2) {
        // ----------------- PRODUCER: 2 warps, 256 rows each -----------------
        const int plane7 = lid & 7;
        const int prbase = wid * 256 + (lid >> 3);   // + k*4, k = 0..63
        int pph[2] = {1, 1};                         // first empty-wait passes
        Cur c_p = {(int)blockIdx.x, 0};

        for (int s = 0; s < S; ++s) {
            const int st = s & 1;
            MBARRIER_WAIT_PARITY(barb + 16 + st * 8, pph[st]);
            pph[st] ^= 1;
            const uint32_t dst = abase0 + st * A_BYTES;
#pragma unroll 1
            for (int kb = 0; kb < 8; ++kb) {
                float4 v[8];
#pragma unroll
                for (int k = 0; k < 8; ++k)
                    v[k] = gather16(idx_raw, is64, c_p, prbase + (kb * 8 + k) * 4, plane7);
#pragma unroll
                for (int k = 0; k < 8; ++k)
                    sts128(dst + (uint32_t)(prbase + (kb * 8 + k) * 4) * A_PITCH_B
                               + plane7 * 16, v[k]);
            }
            MBARRIER_ARRIVE(barb + st * 8);          // release: full
            adv(c_p, gridDim.x);
        }
    } else {
        // ----------------- CONSUMER: 16 warps, 32 px x 64 co each -----------
        const int cwid = wid - 2;                    // 0..15
        const int gid = lid >> 2;
        const int tig = lid & 3;
        const uint32_t bsw = (uint32_t)((lid >> 1) & 3);
        const int lm = lid >> 3, lr = lid & 7;
        const uint32_t lconst = (uint32_t)(((lm & 1) * 8 + lr) * A_PITCH_B
                                           + (lm >> 1) * 16 + cwid * 32 * A_PITCH_B);
        int cph[2] = {0, 0};
        Cur c_cmp = {(int)blockIdx.x, 0};
        float acc[2][8][4];

        for (int s = 0; s < S; ++s) {
            const int st = s & 1;
            MBARRIER_WAIT_PARITY(barb + st * 8, cph[st]);
            cph[st] ^= 1;

            if (c_cmp.tap == 0) {
#pragma unroll
                for (int mh = 0; mh < 2; ++mh)
#pragma unroll
                    for (int nt = 0; nt < 8; ++nt)
#pragma unroll
                        for (int q = 0; q < 4; ++q) acc[mh][nt][q] = 0.f;
            }

            const uint32_t ab   = abase0 + st * A_BYTES;
            const uint32_t wtap = wbase + (uint32_t)c_cmp.tap * W_TAP_B
                                + (uint32_t)lid * 64;
#pragma unroll
            for (int ks = 0; ks < 4; ++ks) {
                uint32_t a[2][4];
#pragma unroll
                for (int mh = 0; mh < 2; ++mh)
                    ldmatrix_x4(a[mh], ab + lconst + mh * (16 * A_PITCH_B) + ks * 32);
                const uint32_t wks = wtap + (uint32_t)ks * 2048;
#pragma unroll
                for (int c = 0; c < 4; ++c) {
                    uint32_t q[4];
                    lds128(q, wks + ((c ^ bsw) << 4));
                    mma_f16(acc[0][2 * c],     a[0], q[0], q[1]);
                    mma_f16(acc[1][2 * c],     a[1], q[0], q[1]);
                    mma_f16(acc[0][2 * c + 1], a[0], q[2], q[3]);
                    mma_f16(acc[1][2 * c + 1], a[1], q[2], q[3]);
                }
            }

            if (c_cmp.tap == 8) {
                int b  = c_cmp.tile >> 8;
                int pt = c_cmp.tile & (TILES_PER_B - 1);
                float* op = out + ((size_t)b << 23) + (size_t)pt * TILE_P;
#pragma unroll
                for (int mh = 0; mh < 2; ++mh) {
                    int px = cwid * 32 + mh * 16 + gid;
#pragma unroll
                    for (int nt = 0; nt < 8; ++nt) {
                        int co = nt * 8 + 2 * tig;
                        float b0 = bsm[co], b1 = bsm[co + 1];
                        float* q = op + (size_t)co * HW + px;
                        q[0]      = acc[mh][nt][0] + b0;
                        q[HW]     = acc[mh][nt][1] + b1;
                        q[8]      = acc[mh][nt][2] + b0;
                        q[HW + 8] = acc[mh][nt][3] + b1;
                    }
                }
            }

            MBARRIER_ARRIVE(barb + 16 + st * 8);     // empty
            adv(c_cmp, gridDim.x);
        }
    }
}

// ---------------------------------------------------------------------------
// Launch
// ---------------------------------------------------------------------------
extern "C" void kernel_launch(void* const* d_in, const int* in_sizes, int n_in,
                              void* d_out, int out_size) {
    const float* x    = (const float*)d_in[0];
    const void*  idx  = d_in[1];
    const float* wgt  = (const float*)d_in[2];
    const float* bias = (const float*)d_in[3];
    float* out        = (float*)d_out;

    dim3 tb(32, 8);
    dim3 tg(HW / 32, C_ / 32, B_);
    transpose_kernel<<<tg, tb>>>(x, (const unsigned int*)idx);

    cudaFuncSetAttribute(latconv_main, cudaFuncAttributeMaxDynamicSharedMemorySize,
                         SMEM_TOTAL);
    int sm_count = 0;
    cudaDeviceGetAttribute(&sm_count, cudaDevAttrMultiProcessorCount, 0);
    if (sm_count <= 0) sm_count = 148;

    latconv_main<<<sm_count, THREADS, SMEM_TOTAL>>>(idx, wgt, bias, out);
}

// round 15
// speedup vs baseline: 2.3043x; 2.3043x over previous
#include <cuda_runtime.h>
#include <cuda_fp16.h>
#include <cstdint>

// ---------------------------------------------------------------------------
// Problem constants
// ---------------------------------------------------------------------------
static constexpr int B_  = 4;
static constexpr int C_  = 64;
static constexpr int H_  = 256;
static constexpr int W_  = 512;
static constexpr int HW  = H_ * W_;               // 131072 = 2^17
static constexpr int SW_ = 3 * W_;                // 1536
static constexpr int TILE_P = 512;                // one full image row
static constexpr int TILES_PER_B = HW / TILE_P;   // 256
static constexpr int N_TILES = B_ * TILES_PER_B;  // 1024
static constexpr int THREADS = 512;               // 16 warps, 32 px/warp

// A stages: 512 px rows x 144B pitch (128B data + 16B pad, ldmatrix-friendly)
static constexpr int A_PITCH_B = 144;
static constexpr int A_BYTES   = TILE_P * A_PITCH_B;        // 73728
// W: per-thread B-fragment records: [tap][ks][lane] 64B, chunk-XOR swizzled
static constexpr int W_TAP_B   = 4 * 2048;                  // 8192
static constexpr int W_BYTES   = 9 * W_TAP_B;               // 73728

static constexpr int SMEM_W    = 0;
static constexpr int SMEM_BIAS = W_BYTES;                   // 256 B
static constexpr int SMEM_BAR  = W_BYTES + 256;             // 4 x 8B mbarriers
static constexpr int SMEM_A    = W_BYTES + 512;             // 74240 (128-aligned)
static constexpr int SMEM_TOTAL = SMEM_A + 2 * A_BYTES;     // 221696

__device__ int    g_idx_is64;
__device__ __align__(128) __half g_xt[(size_t)B_ * HW * C_];  // [B][HW][C] fp16

// ---------------------------------------------------------------------------
// PTX helpers
// ---------------------------------------------------------------------------
__device__ __forceinline__ uint32_t smem_u32(const void* p) {
    uint32_t a;
    asm("{ .reg .u64 t; cvta.to.shared.u64 t, %1; cvt.u32.u64 %0, t; }" : "=r"(a) : "l"(p));
    return a;
}

__device__ __forceinline__ void ldmatrix_x4(uint32_t* r, uint32_t addr) {
    asm volatile("ldmatrix.sync.aligned.m8n8.x4.shared.b16 {%0,%1,%2,%3}, [%4];"
                 : "=r"(r[0]), "=r"(r[1]), "=r"(r[2]), "=r"(r[3]) : "r"(addr));
}

__device__ __forceinline__ void lds128(uint32_t* q, uint32_t addr) {
    asm volatile("ld.shared.v4.b32 {%0,%1,%2,%3}, [%4];"
                 : "=r"(q[0]), "=r"(q[1]), "=r"(q[2]), "=r"(q[3]) : "r"(addr));
}

__device__ __forceinline__ void mma_f16(float* c, const uint32_t* a, uint32_t b0, uint32_t b1) {
    asm volatile(
        "mma.sync.aligned.m16n8k16.row.col.f32.f16.f16.f32 "
        "{%0,%1,%2,%3}, {%4,%5,%6,%7}, {%8,%9}, {%0,%1,%2,%3};"
        : "+f"(c[0]), "+f"(c[1]), "+f"(c[2]), "+f"(c[3])
        : "r"(a[0]), "r"(a[1]), "r"(a[2]), "r"(a[3]), "r"(b0), "r"(b1));
}

__device__ __forceinline__ void sts128(uint32_t addr, float4 v) {
    asm volatile("st.shared.v4.b32 [%0], {%1,%2,%3,%4};"
                 :: "r"(addr), "f"(v.x), "f"(v.y), "f"(v.z), "f"(v.w) : "memory");
}

#define MBARRIER_INIT(bar, cnt) \
    asm volatile("mbarrier.init.shared.b64 [%0], %1;" :: "r"(bar), "r"((uint32_t)(cnt)) : "memory")

#define MBARRIER_ARRIVE(bar) \
    asm volatile("mbarrier.arrive.release.cta.shared::cta.b64 _, [%0];" :: "r"(bar) : "memory")

#define MBARRIER_WAIT_PARITY(bar, ph) do {                                              \
    uint32_t _m = (bar); uint32_t _p = (ph); uint32_t _d;                               \
    asm volatile("{\n\t.reg .pred p;\n\t"                                               \
        "mbarrier.try_wait.parity.acquire.cta.shared::cta.b64 p, [%1], %2;\n\t"         \
        "selp.b32 %0, 1, 0, p;\n\t}" : "=r"(_d) : "r"(_m), "r"(_p) : "memory");         \
    if (!_d) {                                                                          \
        asm volatile("{\n\t.reg .pred P1;\n\t"                                          \
            "WL_%=:\n\t"                                                                \
            "mbarrier.try_wait.parity.acquire.cta.shared::cta.b64 P1, [%0], %1, 0x989680;\n\t" \
            "@P1 bra.uni WD_%=;\n\t"                                                    \
            "bra.uni WL_%=;\n\t"                                                        \
            "WD_%=:\n\t}" :: "r"(_m), "r"(_p) : "memory");                              \
    }                                                                                   \
} while (0)

// ---------------------------------------------------------------------------
// Kernel 1: transpose x [B][C][HW] -> g_xt [B][HW][C] fp16; block (0,0,0)
//           also detects idx dtype (int64 vs int32).
// ---------------------------------------------------------------------------
__global__ void transpose_kernel(const float* __restrict__ x,
                                 const unsigned int* __restrict__ idxw) {
    if (blockIdx.x == 0 && blockIdx.y == 0 && blockIdx.z == 0 &&
        threadIdx.x == 0 && threadIdx.y == 0) {
        int is64 = 1;
        for (int i = 0; i < 64; ++i)
            if (idxw[2 * i + 1] != 0u) { is64 = 0; break; }
        g_idx_is64 = is64;
    }
    __shared__ float t[32][33];
    const int b  = blockIdx.z;
    const int cb = blockIdx.y * 32;
    const int gb = blockIdx.x * 32;
    const int tx = threadIdx.x, ty = threadIdx.y;
    const float* xb = x + (size_t)b * C_ * HW;
#pragma unroll
    for (int i = 0; i < 32; i += 8)
        t[ty + i][tx] = xb[(size_t)(cb + ty + i) * HW + gb + tx];
    __syncthreads();
    __half* xtb = g_xt + ((size_t)b * HW) * C_;
    const int c2  = tx & 15;
    const int sel = tx >> 4;
#pragma unroll
    for (int i = 0; i < 2; ++i) {
        int hwl = ty * 4 + sel * 2 + i;
        __half2 v = __floats2half2_rn(t[2 * c2][hwl], t[2 * c2 + 1][hwl]);
        *(__half2*)(xtb + (size_t)(gb + hwl) * C_ + cb + 2 * c2) = v;
    }
}

// ---------------------------------------------------------------------------
// Kernel 2: persistent fused gather (LDG.128 + STS.128, 2-stage ring) + fp16
//           mma.sync.  Split arrive/wait mbarrier pipeline (NO lockstep
//           __syncthreads in the loop):
//             f_k (full):  arrive after STS into stage k; wait before compute k
//             e_k (empty): arrive after last read of stage k; wait before STS k
//           A fast warp can run a full step ahead -> gather (LSU) of some
//           warps overlaps mma of others on every SMSP.
// ---------------------------------------------------------------------------
struct Cur { int tile; int tap; };
__device__ __forceinline__ void adv(Cur& c, int stride) {
    if (++c.tap == 9) { c.tap = 0; c.tile += stride; }
}

__device__ __forceinline__ float4 gather16(const void* idx, int is64,
                                           const Cur& c, int row, int lane7) {
    int pt = c.tile & (TILES_PER_B - 1);       // image row
    int kh = c.tap / 3;
    int kw = c.tap - kh * 3;
    int o  = (3 * pt + kh) * SW_ + 3 * row + kw;
    int g  = is64 ? (int)__ldg((const long long*)idx + o)
                  : __ldg((const int*)idx + o);
    const char* src = (const char*)g_xt
                    + ((((size_t)(c.tile >> 8)) << 17) + (uint32_t)g) * (C_ * 2)
                    + lane7 * 16;
    return __ldg((const float4*)src);
}

__global__ void __launch_bounds__(THREADS, 1)
latconv_main(const void* __restrict__ idx_raw,
             const float* __restrict__ wgt,
             const float* __restrict__ bias,
             float* __restrict__ out) {
    extern __shared__ char smem[];
    const uint32_t wbase = smem_u32(smem + SMEM_W);
    float* bsm = (float*)(smem + SMEM_BIAS);

    const int tid = threadIdx.x;
    const int wid = tid >> 5;       // 0..15
    const int lid = tid & 31;
    const int gid = lid >> 2;       // 0..7
    const int tig = lid & 3;        // 0..3
    const int is64 = g_idx_is64;
    const uint32_t bsw = (uint32_t)((lid >> 1) & 3);   // B chunk swizzle

    // gather lane mapping: 8 lanes per row -> each warp-LDG.128 covers 4 rows
    const int lane7 = lid & 7;
    const int rbase = wid * 32 + (lid >> 3);   // + k*4 for k = 0..7

    // ldmatrix per-lane address constant (16x16 A tiles, 144B pitch)
    const int lm = lid >> 3, lr = lid & 7;
    const uint32_t lconst = (uint32_t)(((lm & 1) * 8 + lr) * A_PITCH_B
                                       + (lm >> 1) * 16 + wid * 32 * A_PITCH_B);

    // Stage weights fp16 as per-thread B-fragment records (r12 layout).
    for (int e = tid; e < C_ * C_ * 9; e += THREADS) {
        int ci = e & 63, co = (e >> 6) & 63, j = e >> 12;
        int nt = co >> 3, gw = co & 7;
        int ks = ci >> 4, r = ci & 15;
        int bsel = r >> 3, tw = (r & 7) >> 1, lo = r & 1;
        int lane = gw * 4 + tw;
        int c = nt >> 1, u = ((nt & 1) << 1) + bsel;
        uint32_t off = (uint32_t)(j * W_TAP_B + ks * 2048 + lane * 64
                     + ((c ^ ((lane >> 1) & 3)) << 4) + (u << 2) + (lo << 1));
        *(__half*)(smem + SMEM_W + off) = __float2half_rn(wgt[co * 576 + ci * 9 + j]);
    }
    if (tid < C_) bsm[tid] = bias[tid];

    const uint32_t barb   = smem_u32(smem + SMEM_BAR);
    const uint32_t abase0 = smem_u32(smem + SMEM_A);
    // f0 @ +0, f1 @ +8, e0 @ +16, e1 @ +24; all count = THREADS
    if (tid == 0) {
#pragma unroll
        for (int i = 0; i < 4; ++i) MBARRIER_INIT(barb + 8 * i, THREADS);
    }
    __syncthreads();

    const int nloc = (N_TILES - (int)blockIdx.x + (int)gridDim.x - 1) / (int)gridDim.x;
    const int S = nloc * 9;
    if (S == 0) return;

    // prologue: fill stage 0 with step-0 data; arrive f0. Pre-arrive e1 so the
    // first STS into stage 1 (step 0) passes its empty-wait.
    Cur c0 = {(int)blockIdx.x, 0};
    {
#pragma unroll
        for (int k = 0; k < 8; ++k) {
            float4 v = gather16(idx_raw, is64, c0, rbase + k * 4, lane7);
            sts128(abase0 + (uint32_t)(rbase + k * 4) * A_PITCH_B + lane7 * 16, v);
        }
        MBARRIER_ARRIVE(barb + 0);      // f0: stage 0 filled (my share)
        MBARRIER_ARRIVE(barb + 24);     // e1: stage 1 "already consumed"
    }
    Cur c_iss = c0; adv(c_iss, gridDim.x);     // gathers for step s+1
    Cur c_cmp = {(int)blockIdx.x, 0};

    int fph[2] = {0, 0};   // phases for f0/f1 waits
    int eph[2] = {0, 0};   // phases for e0/e1 waits

    float acc[2][8][4];

    for (int s = 0; s < S; ++s) {
        const int  st   = s & 1;
        const int  sn   = st ^ 1;
        const bool have = (s + 1 < S);
        const uint32_t ab = abase0 + st * A_BYTES;
        const uint32_t an = abase0 + sn * A_BYTES;

        // batch-A gather LDGs for step s+1 (before the full-wait: latency
        // overlaps the barrier)
        float4 stg[4];
        if (have) {
#pragma unroll
            for (int k = 0; k < 4; ++k)
                stg[k] = gather16(idx_raw, is64, c_iss, rbase + k * 4, lane7);
        }

        // wait: stage st filled by all warps
        MBARRIER_WAIT_PARITY(barb + st * 8, fph[st]);
        fph[st] ^= 1;

        if (c_cmp.tap == 0) {
#pragma unroll
            for (int mh = 0; mh < 2; ++mh)
#pragma unroll
                for (int nt = 0; nt < 8; ++nt)
#pragma unroll
                    for (int q = 0; q < 4; ++q) acc[mh][nt][q] = 0.f;
        }

        const uint32_t wtap = wbase + (uint32_t)c_cmp.tap * W_TAP_B
                            + (uint32_t)lid * 64;

        // compute ks = 0,1
#pragma unroll
        for (int ks = 0; ks < 2; ++ks) {
            uint32_t a[2][4];
#pragma unroll
            for (int mh = 0; mh < 2; ++mh)
                ldmatrix_x4(a[mh], ab + lconst + mh * (16 * A_PITCH_B) + ks * 32);
            const uint32_t wks = wtap + (uint32_t)ks * 2048;
#pragma unroll
            for (int c = 0; c < 4; ++c) {
                uint32_t q[4];
                lds128(q, wks + ((c ^ bsw) << 4));
                mma_f16(acc[0][2 * c],     a[0], q[0], q[1]);
                mma_f16(acc[1][2 * c],     a[1], q[0], q[1]);
                mma_f16(acc[0][2 * c + 1], a[0], q[2], q[3]);
                mma_f16(acc[1][2 * c + 1], a[1], q[2], q[3]);
            }
        }

        // stage sn consumable? then store batch A, launch batch B
        if (have) {
            MBARRIER_WAIT_PARITY(barb + 16 + sn * 8, eph[sn]);
            eph[sn] ^= 1;
#pragma unroll
            for (int k = 0; k < 4; ++k)
                sts128(an + (uint32_t)(rbase + k * 4) * A_PITCH_B + lane7 * 16, stg[k]);
#pragma unroll
            for (int k = 0; k < 4; ++k)
                stg[k] = gather16(idx_raw, is64, c_iss, rbase + (k + 4) * 4, lane7);
        }

        // compute ks = 2,3
#pragma unroll
        for (int ks = 2; ks < 4; ++ks) {
            uint32_t a[2][4];
#pragma unroll
            for (int mh = 0; mh < 2; ++mh)
                ldmatrix_x4(a[mh], ab + lconst + mh * (16 * A_PITCH_B) + ks * 32);
            const uint32_t wks = wtap + (uint32_t)ks * 2048;
#pragma unroll
            for (int c = 0; c < 4; ++c) {
                uint32_t q[4];
                lds128(q, wks + ((c ^ bsw) << 4));
                mma_f16(acc[0][2 * c],     a[0], q[0], q[1]);
                mma_f16(acc[1][2 * c],     a[1], q[0], q[1]);
                mma_f16(acc[0][2 * c + 1], a[0], q[2], q[3]);
                mma_f16(acc[1][2 * c + 1], a[1], q[2], q[3]);
            }
        }

        // done reading stage st
        MBARRIER_ARRIVE(barb + 16 + st * 8);

        // store batch B; stage sn filled
        if (have) {
#pragma unroll
            for (int k = 0; k < 4; ++k)
                sts128(an + (uint32_t)(rbase + (k + 4) * 4) * A_PITCH_B + lane7 * 16, stg[k]);
            MBARRIER_ARRIVE(barb + sn * 8);
        }

        if (c_cmp.tap == 8) {
            // epilogue: direct STG from accumulators
            int b  = c_cmp.tile >> 8;
            int pt = c_cmp.tile & (TILES_PER_B - 1);
            float* op = out + ((size_t)b << 23) + (size_t)pt * TILE_P;
#pragma unroll
            for (int mh = 0; mh < 2; ++mh) {
                int px = wid * 32 + mh * 16 + gid;
#pragma unroll
                for (int nt = 0; nt < 8; ++nt) {
                    int co = nt * 8 + 2 * tig;
                    float b0 = bsm[co], b1 = bsm[co + 1];
                    float* q = op + (size_t)co * HW + px;
                    q[0]      = acc[mh][nt][0] + b0;
                    q[HW]     = acc[mh][nt][1] + b1;
                    q[8]      = acc[mh][nt][2] + b0;
                    q[HW + 8] = acc[mh][nt][3] + b1;
                }
            }
        }

        adv(c_iss, gridDim.x);
        adv(c_cmp, gridDim.x);
    }
}

// ---------------------------------------------------------------------------
// Launch
// ---------------------------------------------------------------------------
extern "C" void kernel_launch(void* const* d_in, const int* in_sizes, int n_in,
                              void* d_out, int out_size) {
    const float* x    = (const float*)d_in[0];
    const void*  idx  = d_in[1];
    const float* wgt  = (const float*)d_in[2];
    const float* bias = (const float*)d_in[3];
    float* out        = (float*)d_out;

    dim3 tb(32, 8);
    dim3 tg(HW / 32, C_ / 32, B_);
    transpose_kernel<<<tg, tb>>>(x, (const unsigned int*)idx);

    cudaFuncSetAttribute(latconv_main, cudaFuncAttributeMaxDynamicSharedMemorySize,
                         SMEM_TOTAL);
    int sm_count = 0;
    cudaDeviceGetAttribute(&sm_count, cudaDevAttrMultiProcessorCount, 0);
    if (sm_count <= 0) sm_count = 148;

    latconv_main<<<sm_count, THREADS, SMEM_TOTAL>>>(idx, wgt, bias, out);
}

// round 16
// speedup vs baseline: 2.8566x; 1.2397x over previous
#include <cuda_runtime.h>
#include <cuda_fp16.h>
#include <cstdint>

// ---------------------------------------------------------------------------
// Problem constants
// ---------------------------------------------------------------------------
static constexpr int B_  = 4;
static constexpr int C_  = 64;
static constexpr int H_  = 256;
static constexpr int W_  = 512;
static constexpr int HW  = H_ * W_;               // 131072 = 2^17
static constexpr int SW_ = 3 * W_;                // 1536
static constexpr int TILE_P = 512;                // one full image row
static constexpr int TILES_PER_B = HW / TILE_P;   // 256
static constexpr int N_TILES = B_ * TILES_PER_B;  // 1024
static constexpr int THREADS = 512;               // 16 warps, 32 px/warp

// W: per-thread B-fragment records: [tap][ks][lane] 64B, chunk-XOR swizzled
static constexpr int W_TAP_B   = 4 * 2048;                  // 8192
static constexpr int W_BYTES   = 9 * W_TAP_B;               // 73728

static constexpr int SMEM_W    = 0;
static constexpr int SMEM_BIAS = W_BYTES;                   // 256 B
static constexpr int SMEM_TOTAL = W_BYTES + 256;            // 73984

__device__ int g_idx_is64;
// xt rows are 128B, intra-row FRAGMENT-PERMUTED:
//   logical channel c -> byte  tig(c)*32 + ks(c)*8 + hi(c)*4 + lo(c)*2
//   with cw=c&15: tig=(cw&7)>>1, hi=cw>>3, lo=c&1, ks=c>>4.
// A thread (tig) then reads its whole-tap fragment share of one row as one
// contiguous 32B block at offset tig*32 (2 x LDG.128).
__device__ __align__(128) __half g_xt[(size_t)B_ * HW * C_];

// ---------------------------------------------------------------------------
// PTX helpers
// ---------------------------------------------------------------------------
__device__ __forceinline__ uint32_t smem_u32(const void* p) {
    uint32_t a;
    asm("{ .reg .u64 t; cvta.to.shared.u64 t, %1; cvt.u32.u64 %0, t; }" : "=r"(a) : "l"(p));
    return a;
}

__device__ __forceinline__ void lds128(uint32_t* q, uint32_t addr) {
    asm volatile("ld.shared.v4.b32 {%0,%1,%2,%3}, [%4];"
                 : "=r"(q[0]), "=r"(q[1]), "=r"(q[2]), "=r"(q[3]) : "r"(addr));
}

__device__ __forceinline__ void mma_f16(float* c, uint32_t a0, uint32_t a1,
                                        uint32_t a2, uint32_t a3,
                                        uint32_t b0, uint32_t b1) {
    asm volatile(
        "mma.sync.aligned.m16n8k16.row.col.f32.f16.f16.f32 "
        "{%0,%1,%2,%3}, {%4,%5,%6,%7}, {%8,%9}, {%0,%1,%2,%3};"
        : "+f"(c[0]), "+f"(c[1]), "+f"(c[2]), "+f"(c[3])
        : "r"(a0), "r"(a1), "r"(a2), "r"(a3), "r"(b0), "r"(b1));
}

// ---------------------------------------------------------------------------
// Kernel 1: transpose x [B][C][HW] -> g_xt [B][HW][C] fp16 with the
//           fragment permutation; block (0,0,0) also detects idx dtype.
// ---------------------------------------------------------------------------
__global__ void transpose_kernel(const float* __restrict__ x,
                                 const unsigned int* __restrict__ idxw) {
    if (blockIdx.x == 0 && blockIdx.y == 0 && blockIdx.z == 0 &&
        threadIdx.x == 0 && threadIdx.y == 0) {
        int is64 = 1;
        for (int i = 0; i < 64; ++i)
            if (idxw[2 * i + 1] != 0u) { is64 = 0; break; }
        g_idx_is64 = is64;
    }
    __shared__ float t[32][33];
    const int b  = blockIdx.z;
    const int cb = blockIdx.y * 32;
    const int gb = blockIdx.x * 32;
    const int tx = threadIdx.x, ty = threadIdx.y;
    const float* xb = x + (size_t)b * C_ * HW;
#pragma unroll
    for (int i = 0; i < 32; i += 8)
        t[ty + i][tx] = xb[(size_t)(cb + ty + i) * HW + gb + tx];
    __syncthreads();
    char* xtb = (char*)g_xt + (((size_t)b * HW) << 7);   // 128B rows
    const int c2v = tx & 15;       // half2 index within this 32-channel slab
    const int sel = tx >> 4;
#pragma unroll
    for (int i = 0; i < 2; ++i) {
        int hwl = ty * 4 + sel * 2 + i;
        __half2 v = __floats2half2_rn(t[2 * c2v][hwl], t[2 * c2v + 1][hwl]);
        int c2g  = (cb >> 1) + c2v;                       // global half2 0..31
        uint32_t byte = (uint32_t)((c2g & 3) * 32 + (c2g >> 3) * 8
                                   + ((c2g >> 2) & 1) * 4);
        *(__half2*)(xtb + (((size_t)(gb + hwl)) << 7) + byte) = v;
    }
}

// ---------------------------------------------------------------------------
// Kernel 2: persistent fused kernel, NO smem A, NO barriers in the loop.
//   Each thread direct-LDGs its mma A fragments from permuted g_xt
//   (8 x LDG.128 per tap), B fragments from smem W records, 64 mma per
//   warp per tap, direct-STG epilogue.  Warps fully independent.
// ---------------------------------------------------------------------------
struct Cur { int tile; int tap; };
__device__ __forceinline__ void adv(Cur& c, int stride) {
    if (++c.tap == 9) { c.tap = 0; c.tile += stride; }
}

__global__ void __launch_bounds__(THREADS, 1)
latconv_main(const void* __restrict__ idx_raw,
             const float* __restrict__ wgt,
             const float* __restrict__ bias,
             float* __restrict__ out) {
    extern __shared__ char smem[];
    const uint32_t wbase = smem_u32(smem + SMEM_W);
    float* bsm = (float*)(smem + SMEM_BIAS);

    const int tid = threadIdx.x;
    const int wid = tid >> 5;       // 0..15
    const int lid = tid & 31;
    const int gid = lid >> 2;       // 0..7
    const int tig = lid & 3;        // 0..3
    const int is64 = g_idx_is64;
    const uint32_t bsw = (uint32_t)((lid >> 1) & 3);   // B chunk swizzle

    // Stage weights fp16 as per-thread B-fragment records (r12 layout).
    for (int e = tid; e < C_ * C_ * 9; e += THREADS) {
        int ci = e & 63, co = (e >> 6) & 63, j = e >> 12;
        int nt = co >> 3, gw = co & 7;
        int ks = ci >> 4, r = ci & 15;
        int bsel = r >> 3, tw = (r & 7) >> 1, lo = r & 1;
        int lane = gw * 4 + tw;
        int c = nt >> 1, u = ((nt & 1) << 1) + bsel;
        uint32_t off = (uint32_t)(j * W_TAP_B + ks * 2048 + lane * 64
                     + ((c ^ ((lane >> 1) & 3)) << 4) + (u << 2) + (lo << 1));
        *(__half*)(smem + SMEM_W + off) = __float2half_rn(wgt[co * 576 + ci * 9 + j]);
    }
    if (tid < C_) bsm[tid] = bias[tid];
    __syncthreads();

    // my 4 fragment rows within the tile: wid*32 + rsel*8 + gid
    const int myrow = wid * 32 + gid;

    // idx cursor: gi[] holds indices for the step about to be computed;
    // c_nxt points at the step AFTER that (prefetch target).
    Cur c_nxt = {(int)blockIdx.x, 0};
    int gi[4];
    {
        int pt = c_nxt.tile & (TILES_PER_B - 1);
        int o0 = 3 * pt * SW_;     // tap 0: kh=0, kw=0
#pragma unroll
        for (int rs = 0; rs < 4; ++rs) {
            int o = o0 + 3 * (myrow + rs * 8);
            gi[rs] = is64 ? (int)__ldg((const long long*)idx_raw + o)
                          : __ldg((const int*)idx_raw + o);
        }
    }
    adv(c_nxt, gridDim.x);

    float acc[2][8][4];

    for (int tile = blockIdx.x; tile < N_TILES; tile += gridDim.x) {
        const char* base = (const char*)g_xt + ((size_t)(tile >> 8) << 24);

#pragma unroll 1
        for (int j = 0; j < 9; ++j) {
            // ---- issue A fragment loads for this tap (uses gi) ----
            uint32_t ar[4][8];
#pragma unroll
            for (int rs = 0; rs < 4; ++rs) {
                const char* rb = base + ((uint32_t)gi[rs] << 7) + tig * 32;
                uint4 v0 = __ldg((const uint4*)rb);
                uint4 v1 = __ldg((const uint4*)(rb + 16));
                ar[rs][0] = v0.x; ar[rs][1] = v0.y;
                ar[rs][2] = v0.z; ar[rs][3] = v0.w;
                ar[rs][4] = v1.x; ar[rs][5] = v1.y;
                ar[rs][6] = v1.z; ar[rs][7] = v1.w;
            }

            // ---- prefetch idx for the next step ----
            if (c_nxt.tile < N_TILES) {
                int pt = c_nxt.tile & (TILES_PER_B - 1);
                int kh = c_nxt.tap / 3;
                int kw = c_nxt.tap - kh * 3;
                int ob = (3 * pt + kh) * SW_ + kw;
#pragma unroll
                for (int rs = 0; rs < 4; ++rs) {
                    int o = ob + 3 * (myrow + rs * 8);
                    gi[rs] = is64 ? (int)__ldg((const long long*)idx_raw + o)
                                  : __ldg((const int*)idx_raw + o);
                }
            }
            adv(c_nxt, gridDim.x);

            if (j == 0) {
#pragma unroll
                for (int mh = 0; mh < 2; ++mh)
#pragma unroll
                    for (int nt = 0; nt < 8; ++nt)
#pragma unroll
                        for (int q = 0; q < 4; ++q) acc[mh][nt][q] = 0.f;
            }

            // ---- compute: 4 ks x (4 B-lds128 + 16 mma) ----
            const uint32_t wtap = wbase + (uint32_t)j * W_TAP_B
                                + (uint32_t)lid * 64;
#pragma unroll
            for (int ks = 0; ks < 4; ++ks) {
                const uint32_t wks = wtap + (uint32_t)ks * 2048;
#pragma unroll
                for (int c = 0; c < 4; ++c) {
                    uint32_t q[4];
                    lds128(q, wks + ((c ^ bsw) << 4));
                    mma_f16(acc[0][2 * c],
                            ar[0][2 * ks], ar[1][2 * ks],
                            ar[0][2 * ks + 1], ar[1][2 * ks + 1], q[0], q[1]);
                    mma_f16(acc[1][2 * c],
                            ar[2][2 * ks], ar[3][2 * ks],
                            ar[2][2 * ks + 1], ar[3][2 * ks + 1], q[0], q[1]);
                    mma_f16(acc[0][2 * c + 1],
                            ar[0][2 * ks], ar[1][2 * ks],
                            ar[0][2 * ks + 1], ar[1][2 * ks + 1], q[2], q[3]);
                    mma_f16(acc[1][2 * c + 1],
                            ar[2][2 * ks], ar[3][2 * ks],
                            ar[2][2 * ks + 1], ar[3][2 * ks + 1], q[2], q[3]);
                }
            }
        }

        // ---- epilogue: direct STG from accumulators ----
        {
            int b  = tile >> 8;
            int pt = tile & (TILES_PER_B - 1);
            float* op = out + ((size_t)b << 23) + (size_t)pt * TILE_P;
#pragma unroll
            for (int mh = 0; mh < 2; ++mh) {
                int px = wid * 32 + mh * 16 + gid;
#pragma unroll
                for (int nt = 0; nt < 8; ++nt) {
                    int co = nt * 8 + 2 * tig;
                    float b0 = bsm[co], b1 = bsm[co + 1];
                    float* q = op + (size_t)co * HW + px;
                    q[0]      = acc[mh][nt][0] + b0;
                    q[HW]     = acc[mh][nt][1] + b1;
                    q[8]      = acc[mh][nt][2] + b0;
                    q[HW + 8] = acc[mh][nt][3] + b1;
                }
            }
        }
    }
}

// ---------------------------------------------------------------------------
// Launch
// ---------------------------------------------------------------------------
extern "C" void kernel_launch(void* const* d_in, const int* in_sizes, int n_in,
                              void* d_out, int out_size) {
    const float* x    = (const float*)d_in[0];
    const void*  idx  = d_in[1];
    const float* wgt  = (const float*)d_in[2];
    const float* bias = (const float*)d_in[3];
    float* out        = (float*)d_out;

    dim3 tb(32, 8);
    dim3 tg(HW / 32, C_ / 32, B_);
    transpose_kernel<<<tg, tb>>>(x, (const unsigned int*)idx);

    cudaFuncSetAttribute(latconv_main, cudaFuncAttributeMaxDynamicSharedMemorySize,
                         SMEM_TOTAL);
    int sm_count = 0;
    cudaDeviceGetAttribute(&sm_count, cudaDevAttrMultiProcessorCount, 0);
    if (sm_count <= 0) sm_count = 148;

    latconv_main<<<sm_count, THREADS, SMEM_TOTAL>>>(idx, wgt, bias, out);
}